// round 4
// baseline (speedup 1.0000x reference)
#include <cuda_runtime.h>
#include <math.h>

#define E 256
#define NCAMS 6
#define NLVL 4
#define NPTS 13
#define NG 8
#define NA 900
#define BS 2
#define NATOT (BS*NA)          /* 1800 */
#define SPA (NCAMS*NLVL*NPTS)  /* 312 */
#define JW (NLVL*NPTS*NG)      /* 416 */

/* transposed feature maps: concat over levels of [12][P_l][256] */
#define FMT_TOTAL 45957120
__device__ float g_fmt[FMT_TOTAL];
__device__ float g_ceW[BS*NCAMS*JW];       /* includes wfc_b */
__device__ float g_featw[NATOT*JW];
__device__ int   g_soff[NATOT*SPA*4];
__device__ float g_sw[NATOT*SPA*4];
__device__ float g_wg[NATOT*SPA*NG];
__device__ float g_fused[NATOT*E];

__constant__ int   c_W[4]    = {176, 88, 44, 22};
__constant__ int   c_H[4]    = {64, 32, 16, 8};
__constant__ int   c_base[4] = {0, 34603008, 43253760, 45416448};
__constant__ float c_FIX[7][3] = {
    {0.f,0.f,0.f},{0.45f,0.f,0.f},{-0.45f,0.f,0.f},{0.f,0.45f,0.f},
    {0.f,-0.45f,0.f},{0.f,0.f,0.45f},{0.f,0.f,-0.45f}};

/* ------------- transpose [12][256][P] -> g_fmt(base)+[12][P][256] ------------- */
__global__ void k_transpose(const float* __restrict__ src, int P, int base) {
    __shared__ float tile[32][33];
    int bc = blockIdx.z;
    int ch0 = blockIdx.y * 32;
    int p0 = blockIdx.x * 32;
    int tx = threadIdx.x, ty = threadIdx.y;   /* 32 x 8 */
    const float* s = src + (size_t)bc * 256 * P;
    float* d = g_fmt + base + (size_t)bc * P * 256;
#pragma unroll
    for (int r = 0; r < 4; r++) {
        int ch = ch0 + ty + r * 8;
        int p = p0 + tx;
        if (p < P) tile[ty + r * 8][tx] = s[(size_t)ch * P + p];
    }
    __syncthreads();
#pragma unroll
    for (int r = 0; r < 4; r++) {
        int p = p0 + ty + r * 8;
        int ch = ch0 + tx;
        if (p < P) d[(size_t)p * 256 + ch] = tile[tx][ty + r * 8];
    }
}

/* ------------- block reduction helper ------------- */
__device__ __forceinline__ float block_reduce_sum(float v, float* red) {
    __syncthreads();  /* protect red reuse */
    for (int o = 16; o > 0; o >>= 1) v += __shfl_xor_sync(0xffffffffu, v, o);
    if ((threadIdx.x & 31) == 0) red[threadIdx.x >> 5] = v;
    __syncthreads();
    float s = 0.f;
#pragma unroll
    for (int i = 0; i < 8; i++) s += red[i];
    return s;
}

/* ------------- camera embedding -> ceW (folds wfc_b) ------------- */
__global__ void k_cam(const float* __restrict__ proj,
                      const float* __restrict__ ce1w, const float* __restrict__ ce1b,
                      const float* __restrict__ ln1g, const float* __restrict__ ln1b,
                      const float* __restrict__ ce2w, const float* __restrict__ ce2b,
                      const float* __restrict__ ln2g, const float* __restrict__ ln2b,
                      const float* __restrict__ wfcw, const float* __restrict__ wfcb) {
    int bc = blockIdx.x;
    int t = threadIdx.x;
    __shared__ float cam[12];
    __shared__ float h[256];
    __shared__ float red[8];
    if (t < 12) cam[t] = proj[bc * 16 + t];  /* first 12 floats = rows 0..2 */
    __syncthreads();

    float x = ce1b[t];
    for (int k = 0; k < 12; k++) x += cam[k] * ce1w[k * 256 + t];
    x = fmaxf(x, 0.f);
    {
        float m = block_reduce_sum(x, red) * (1.f / 256.f);
        float d = x - m;
        float var = block_reduce_sum(d * d, red) * (1.f / 256.f);
        x = d * rsqrtf(var + 1e-5f) * ln1g[t] + ln1b[t];
    }
    __syncthreads();
    h[t] = x;
    __syncthreads();

    float y = ce2b[t];
    for (int k = 0; k < 256; k++) y += h[k] * ce2w[k * 256 + t];
    y = fmaxf(y, 0.f);
    {
        float m = block_reduce_sum(y, red) * (1.f / 256.f);
        float d = y - m;
        float var = block_reduce_sum(d * d, red) * (1.f / 256.f);
        y = d * rsqrtf(var + 1e-5f) * ln2g[t] + ln2b[t];
    }
    __syncthreads();
    h[t] = y;
    __syncthreads();

    for (int j = t; j < JW; j += 256) {
        float a = wfcb[j];
        for (int k = 0; k < 256; k++) a += h[k] * wfcw[k * JW + j];
        g_ceW[bc * JW + j] = a;
    }
}

/* ------------- featW = (inst + ae) @ wfc_w, tiled 8 anchors ------------- */
__global__ void k_featw(const float* __restrict__ instf,
                        const float* __restrict__ ae,
                        const float* __restrict__ wfcw) {
    int a0 = blockIdx.x * 8;
    int t = threadIdx.x;
    __shared__ float f[8][256];
#pragma unroll
    for (int aa = 0; aa < 8; aa++)
        f[aa][t] = instf[(a0 + aa) * 256 + t] + ae[(a0 + aa) * 256 + t];
    __syncthreads();
    for (int j = t; j < JW; j += 256) {
        float acc[8];
#pragma unroll
        for (int aa = 0; aa < 8; aa++) acc[aa] = 0.f;
        for (int k = 0; k < 256; k++) {
            float w = wfcw[k * JW + j];
#pragma unroll
            for (int aa = 0; aa < 8; aa++) acc[aa] += f[aa][k] * w;
        }
#pragma unroll
        for (int aa = 0; aa < 8; aa++) g_featw[(a0 + aa) * JW + j] = acc[aa];
    }
}

/* ------------- per-anchor prep: keypoints, projection, sample meta, softmax ------------- */
__global__ void k_prep(const float* __restrict__ anchor,
                       const float* __restrict__ instf,
                       const float* __restrict__ proj,
                       const float* __restrict__ wh,
                       const float* __restrict__ lfcw,
                       const float* __restrict__ lfcb) {
    int a = blockIdx.x;
    int b = a / NA;
    int t = threadIdx.x;
    __shared__ float if_sh[256];
    __shared__ float fw_sh[JW];
    __shared__ float anc[11];
    __shared__ float ls_sh[18];
    __shared__ float kp_sh[39];
    __shared__ float u_sh[78], v_sh[78];
    __shared__ float pr[96];
    __shared__ float whs[12];
    __shared__ float esh[NG * SPA];  /* 2496 */

    if_sh[t] = instf[a * 256 + t];
    fw_sh[t] = g_featw[a * JW + t];
    if (t < JW - 256) fw_sh[t + 256] = g_featw[a * JW + 256 + t];
    if (t < 11) anc[t] = anchor[a * 11 + t];
    if (t < 96) pr[t] = proj[b * 96 + t];
    if (t < 12) whs[t] = wh[b * 12 + t];
    __syncthreads();

    if (t < 18) {
        float s = lfcb[t];
        for (int k = 0; k < 256; k++) s += if_sh[k] * lfcw[k * 18 + t];
        ls_sh[t] = 1.f / (1.f + expf(-s)) - 0.5f;
    }
    __syncthreads();

    if (t < NPTS) {
        float sx = expf(anc[3]), sy2 = expf(anc[4]), sz = expf(anc[5]);
        float k0, k1, k2;
        if (t < 7) {
            k0 = c_FIX[t][0] * sx; k1 = c_FIX[t][1] * sy2; k2 = c_FIX[t][2] * sz;
        } else {
            int q = t - 7;
            k0 = ls_sh[q * 3] * sx; k1 = ls_sh[q * 3 + 1] * sy2; k2 = ls_sh[q * 3 + 2] * sz;
        }
        float s6 = anc[6], c7 = anc[7];
        kp_sh[t * 3]     = c7 * k0 - s6 * k1 + anc[0];
        kp_sh[t * 3 + 1] = s6 * k0 + c7 * k1 + anc[1];
        kp_sh[t * 3 + 2] = k2 + anc[2];
    }
    __syncthreads();

    if (t < 78) {
        int c = t / NPTS, p = t % NPTS;
        const float* P4 = pr + c * 16;
        float px = kp_sh[p * 3], py = kp_sh[p * 3 + 1], pz = kp_sh[p * 3 + 2];
        float X = P4[0] * px + P4[1] * py + P4[2] * pz + P4[3];
        float Y = P4[4] * px + P4[5] * py + P4[6] * pz + P4[7];
        float Z = P4[8] * px + P4[9] * py + P4[10] * pz + P4[11];
        Z = fmaxf(Z, 1e-5f);
        float iz = 1.f / Z;
        u_sh[t] = X * iz / whs[c * 2];
        v_sh[t] = Y * iz / whs[c * 2 + 1];
    }
    __syncthreads();

    /* sample metadata: offsets + bilinear*validity weights */
    for (int s = t; s < SPA; s += 256) {
        int c = s / 52, r = s % 52, l = r / NPTS, p = r % NPTS;
        float u = u_sh[c * NPTS + p], v = v_sh[c * NPTS + p];
        int W = c_W[l], H = c_H[l];
        float gx = u * (float)W - 0.5f;
        float gy = v * (float)H - 0.5f;
        float x0f = floorf(gx), y0f = floorf(gy);
        float wx1 = gx - x0f, wy1 = gy - y0f;
        float wx0 = 1.f - wx1, wy0 = 1.f - wy1;
        int pixbase = (b * NCAMS + c) * H * W;
        float tw[4] = {wx0 * wy0, wx1 * wy0, wx0 * wy1, wx1 * wy1};
        float xs[4] = {x0f, x0f + 1.f, x0f, x0f + 1.f};
        float ys[4] = {y0f, y0f, y0f + 1.f, y0f + 1.f};
        int idx4 = (a * SPA + s) * 4;
#pragma unroll
        for (int i = 0; i < 4; i++) {
            float xf = xs[i], yf = ys[i];
            bool ok = (xf >= 0.f) && (xf < (float)W) && (yf >= 0.f) && (yf < (float)H);
            int off = 0; float w = 0.f;
            if (ok) {
                off = c_base[l] + (pixbase + (int)yf * W + (int)xf) * 256;
                w = tw[i];
            }
            g_soff[idx4 + i] = off;
            g_sw[idx4 + i] = w;
        }
    }

    /* softmax over 312 (c,l,p) per group: warp g handles group g */
    int g = t >> 5, lane = t & 31;
    const float* ceWb = g_ceW + b * NCAMS * JW;
    float mx = -1e30f;
    for (int s = lane; s < SPA; s += 32) {
        int c = s / 52; int j = (s % 52) * NG + g;
        float v = fw_sh[j] + ceWb[c * JW + j];
        mx = fmaxf(mx, v);
    }
    for (int o = 16; o > 0; o >>= 1) mx = fmaxf(mx, __shfl_xor_sync(0xffffffffu, mx, o));
    float sum = 0.f;
    for (int s = lane; s < SPA; s += 32) {
        int c = s / 52; int j = (s % 52) * NG + g;
        float v = fw_sh[j] + ceWb[c * JW + j];
        float e = __expf(v - mx);
        esh[g * SPA + s] = e;
        sum += e;
    }
    for (int o = 16; o > 0; o >>= 1) sum += __shfl_xor_sync(0xffffffffu, sum, o);
    float inv = 1.f / sum;
    for (int s = lane; s < SPA; s += 32)
        g_wg[a * (SPA * NG) + s * NG + g] = esh[g * SPA + s] * inv;
}

/* ------------- gather + fuse: block per anchor, thread per channel ------------- */
__global__ void k_sample() {
    int a = blockIdx.x, t = threadIdx.x, g = t >> 5;
    __shared__ int soff[SPA * 4];
    __shared__ float sw[SPA * 4];
    __shared__ float wg[SPA * NG];
    for (int i = t; i < SPA * 4; i += 256) {
        soff[i] = g_soff[a * SPA * 4 + i];
        sw[i] = g_sw[a * SPA * 4 + i];
    }
    for (int i = t; i < SPA * NG; i += 256) wg[i] = g_wg[a * SPA * NG + i];
    __syncthreads();

    float acc = 0.f;
    const float* fmt = g_fmt;
    for (int s = 0; s < SPA; s++) {
        float w0 = sw[s * 4], w1 = sw[s * 4 + 1], w2 = sw[s * 4 + 2], w3 = sw[s * 4 + 3];
        if (w0 == 0.f && w1 == 0.f && w2 == 0.f && w3 == 0.f) continue;
        float wq = wg[s * NG + g];
        float v = 0.f;
        if (w0 != 0.f) v += w0 * fmt[soff[s * 4] + t];
        if (w1 != 0.f) v += w1 * fmt[soff[s * 4 + 1] + t];
        if (w2 != 0.f) v += w2 * fmt[soff[s * 4 + 2] + t];
        if (w3 != 0.f) v += w3 * fmt[soff[s * 4 + 3] + t];
        acc += wq * v;
    }
    g_fused[a * 256 + t] = acc;
}

/* ------------- output projection + concat instance_feature ------------- */
__global__ void k_out(const float* __restrict__ instf,
                      const float* __restrict__ opw,
                      const float* __restrict__ opb,
                      float* __restrict__ out) {
    int a0 = blockIdx.x * 8;
    int t = threadIdx.x;
    __shared__ float f[8][256];
#pragma unroll
    for (int aa = 0; aa < 8; aa++) f[aa][t] = g_fused[(a0 + aa) * 256 + t];
    __syncthreads();
    float acc[8];
#pragma unroll
    for (int aa = 0; aa < 8; aa++) acc[aa] = opb[t];
    for (int k = 0; k < 256; k++) {
        float w = opw[k * 256 + t];
#pragma unroll
        for (int aa = 0; aa < 8; aa++) acc[aa] += f[aa][k] * w;
    }
#pragma unroll
    for (int aa = 0; aa < 8; aa++) {
        out[(size_t)(a0 + aa) * 512 + t] = acc[aa];
        out[(size_t)(a0 + aa) * 512 + 256 + t] = instf[(a0 + aa) * 256 + t];
    }
}

extern "C" void kernel_launch(void* const* d_in, const int* in_sizes, int n_in,
                              void* d_out, int out_size) {
    /* Disambiguate input ordering at runtime (host-side, graph-safe):
       dict order:      3=projection_mat(192), 4=image_wh(24), 5..8=fm0..3
       signature order: 3..6=fm0..3 (fm0 has 34603008 elems), 7=proj, 8=wh   */
    const float* instf = (const float*)d_in[0];
    const float* anchor = (const float*)d_in[1];
    const float* ae = (const float*)d_in[2];
    const float *fm0, *fm1, *fm2, *fm3, *proj, *wh;
    if (in_sizes[3] == 192) {           /* setup_inputs dict order */
        proj = (const float*)d_in[3];
        wh   = (const float*)d_in[4];
        fm0  = (const float*)d_in[5];
        fm1  = (const float*)d_in[6];
        fm2  = (const float*)d_in[7];
        fm3  = (const float*)d_in[8];
    } else {                             /* reference signature order */
        fm0  = (const float*)d_in[3];
        fm1  = (const float*)d_in[4];
        fm2  = (const float*)d_in[5];
        fm3  = (const float*)d_in[6];
        proj = (const float*)d_in[7];
        wh   = (const float*)d_in[8];
    }
    const float* lfcw = (const float*)d_in[9];
    const float* lfcb = (const float*)d_in[10];
    const float* ce1w = (const float*)d_in[11];
    const float* ce1b = (const float*)d_in[12];
    const float* ln1g = (const float*)d_in[13];
    const float* ln1b = (const float*)d_in[14];
    const float* ce2w = (const float*)d_in[15];
    const float* ce2b = (const float*)d_in[16];
    const float* ln2g = (const float*)d_in[17];
    const float* ln2b = (const float*)d_in[18];
    const float* wfcw = (const float*)d_in[19];
    const float* wfcb = (const float*)d_in[20];
    const float* opw = (const float*)d_in[21];
    const float* opb = (const float*)d_in[22];
    float* out = (float*)d_out;

    dim3 tb(32, 8);
    k_transpose<<<dim3((11264 + 31) / 32, 8, 12), tb>>>(fm0, 11264, 0);
    k_transpose<<<dim3((2816 + 31) / 32, 8, 12), tb>>>(fm1, 2816, 34603008);
    k_transpose<<<dim3((704 + 31) / 32, 8, 12), tb>>>(fm2, 704, 43253760);
    k_transpose<<<dim3((176 + 31) / 32, 8, 12), tb>>>(fm3, 176, 45416448);
    k_cam<<<12, 256>>>(proj, ce1w, ce1b, ln1g, ln1b, ce2w, ce2b, ln2g, ln2b, wfcw, wfcb);
    k_featw<<<NATOT / 8, 256>>>(instf, ae, wfcw);
    k_prep<<<NATOT, 256>>>(anchor, instf, proj, wh, lfcw, lfcb);
    k_sample<<<NATOT, 256>>>();
    k_out<<<NATOT / 8, 256>>>(instf, opw, opb, out);
}

// round 7
// speedup vs baseline: 1.1495x; 1.1495x over previous
#include <cuda_runtime.h>
#include <cuda_fp16.h>
#include <math.h>

#define E 256
#define NCAMS 6
#define NLVL 4
#define NPTS 13
#define NG 8
#define NA 900
#define BS 2
#define NATOT (BS*NA)          /* 1800 */
#define SPA (NCAMS*NLVL*NPTS)  /* 312 */
#define JW (NLVL*NPTS*NG)      /* 416 */

/* transposed feature maps (fp16): concat over levels of [12][P_l][256] */
#define FMT_TOTAL 45957120
__device__ __half g_fmt[FMT_TOTAL];
__device__ float g_ceW[BS*NCAMS*JW];       /* includes wfc_b */
__device__ float g_featw[NATOT*JW];
__device__ int   g_soff[NATOT*SPA*4];
__device__ float g_sw[NATOT*SPA*4];
__device__ float g_wg[NATOT*SPA*NG];
__device__ float g_fused[NATOT*E];

__constant__ int   c_W[4]    = {176, 88, 44, 22};
__constant__ int   c_H[4]    = {64, 32, 16, 8};
__constant__ int   c_base[4] = {0, 34603008, 43253760, 45416448};
__constant__ float c_FIX[7][3] = {
    {0.f,0.f,0.f},{0.45f,0.f,0.f},{-0.45f,0.f,0.f},{0.f,0.45f,0.f},
    {0.f,-0.45f,0.f},{0.f,0.f,0.45f},{0.f,0.f,-0.45f}};

/* ------------- transpose [12][256][P] -> g_fmt(base)+[12][P][256] fp16 -------------
   64-channel x 32-p tile; writes half2 (128B per 32-lane row). */
__global__ void k_transpose(const float* __restrict__ src, int P, int base) {
    __shared__ float tile[64][33];
    int bc = blockIdx.z;
    int ch0 = blockIdx.y * 64;
    int p0 = blockIdx.x * 32;
    int tx = threadIdx.x, ty = threadIdx.y;   /* 32 x 8 */
    const float* s = src + (size_t)bc * 256 * P;
    __half* d = g_fmt + base + (size_t)bc * P * 256;
    int p = p0 + tx;
#pragma unroll
    for (int r = 0; r < 8; r++) {
        int chl = ty + r * 8;
        if (p < P) tile[chl][tx] = s[(size_t)(ch0 + chl) * P + p];
    }
    __syncthreads();
#pragma unroll
    for (int r = 0; r < 4; r++) {
        int pl = ty + r * 8;
        int pp = p0 + pl;
        if (pp < P) {
            __half2 h = __float22half2_rn(make_float2(tile[2 * tx][pl], tile[2 * tx + 1][pl]));
            *(__half2*)(d + (size_t)pp * 256 + ch0 + 2 * tx) = h;
        }
    }
}

/* ------------- block reduction helper ------------- */
__device__ __forceinline__ float block_reduce_sum(float v, float* red) {
    __syncthreads();  /* protect red reuse */
    for (int o = 16; o > 0; o >>= 1) v += __shfl_xor_sync(0xffffffffu, v, o);
    if ((threadIdx.x & 31) == 0) red[threadIdx.x >> 5] = v;
    __syncthreads();
    float s = 0.f;
#pragma unroll
    for (int i = 0; i < 8; i++) s += red[i];
    return s;
}

/* ------------- camera embedding -> ceW (folds wfc_b) ------------- */
__global__ void k_cam(const float* __restrict__ proj,
                      const float* __restrict__ ce1w, const float* __restrict__ ce1b,
                      const float* __restrict__ ln1g, const float* __restrict__ ln1b,
                      const float* __restrict__ ce2w, const float* __restrict__ ce2b,
                      const float* __restrict__ ln2g, const float* __restrict__ ln2b,
                      const float* __restrict__ wfcw, const float* __restrict__ wfcb) {
    int bc = blockIdx.x;
    int t = threadIdx.x;
    __shared__ float cam[12];
    __shared__ float h[256];
    __shared__ float red[8];
    if (t < 12) cam[t] = proj[bc * 16 + t];
    __syncthreads();

    float x = ce1b[t];
    for (int k = 0; k < 12; k++) x += cam[k] * ce1w[k * 256 + t];
    x = fmaxf(x, 0.f);
    {
        float m = block_reduce_sum(x, red) * (1.f / 256.f);
        float d = x - m;
        float var = block_reduce_sum(d * d, red) * (1.f / 256.f);
        x = d * rsqrtf(var + 1e-5f) * ln1g[t] + ln1b[t];
    }
    __syncthreads();
    h[t] = x;
    __syncthreads();

    float y = ce2b[t];
    for (int k = 0; k < 256; k++) y += h[k] * ce2w[k * 256 + t];
    y = fmaxf(y, 0.f);
    {
        float m = block_reduce_sum(y, red) * (1.f / 256.f);
        float d = y - m;
        float var = block_reduce_sum(d * d, red) * (1.f / 256.f);
        y = d * rsqrtf(var + 1e-5f) * ln2g[t] + ln2b[t];
    }
    __syncthreads();
    h[t] = y;
    __syncthreads();

    for (int j = t; j < JW; j += 256) {
        float a = wfcb[j];
        for (int k = 0; k < 256; k++) a += h[k] * wfcw[k * JW + j];
        g_ceW[bc * JW + j] = a;
    }
}

/* ------------- featW = (inst + ae) @ wfc_w, tiled 8 anchors ------------- */
__global__ void k_featw(const float* __restrict__ instf,
                        const float* __restrict__ ae,
                        const float* __restrict__ wfcw) {
    int a0 = blockIdx.x * 8;
    int t = threadIdx.x;
    __shared__ float f[8][256];
#pragma unroll
    for (int aa = 0; aa < 8; aa++)
        f[aa][t] = instf[(a0 + aa) * 256 + t] + ae[(a0 + aa) * 256 + t];
    __syncthreads();
    for (int j = t; j < JW; j += 256) {
        float acc[8];
#pragma unroll
        for (int aa = 0; aa < 8; aa++) acc[aa] = 0.f;
        for (int k = 0; k < 256; k++) {
            float w = wfcw[k * JW + j];
#pragma unroll
            for (int aa = 0; aa < 8; aa++) acc[aa] += f[aa][k] * w;
        }
#pragma unroll
        for (int aa = 0; aa < 8; aa++) g_featw[(a0 + aa) * JW + j] = acc[aa];
    }
}

/* ------------- per-anchor prep: keypoints, projection, sample meta, softmax ------------- */
__global__ void k_prep(const float* __restrict__ anchor,
                       const float* __restrict__ instf,
                       const float* __restrict__ proj,
                       const float* __restrict__ wh,
                       const float* __restrict__ lfcw,
                       const float* __restrict__ lfcb) {
    int a = blockIdx.x;
    int b = a / NA;
    int t = threadIdx.x;
    __shared__ float if_sh[256];
    __shared__ float fw_sh[JW];
    __shared__ float anc[11];
    __shared__ float ls_sh[18];
    __shared__ float kp_sh[39];
    __shared__ float u_sh[78], v_sh[78];
    __shared__ float pr[96];
    __shared__ float whs[12];
    __shared__ float esh[NG * SPA];  /* 2496 */

    if_sh[t] = instf[a * 256 + t];
    fw_sh[t] = g_featw[a * JW + t];
    if (t < JW - 256) fw_sh[t + 256] = g_featw[a * JW + 256 + t];
    if (t < 11) anc[t] = anchor[a * 11 + t];
    if (t < 96) pr[t] = proj[b * 96 + t];
    if (t < 12) whs[t] = wh[b * 12 + t];
    __syncthreads();

    if (t < 18) {
        float s = lfcb[t];
        for (int k = 0; k < 256; k++) s += if_sh[k] * lfcw[k * 18 + t];
        ls_sh[t] = 1.f / (1.f + expf(-s)) - 0.5f;
    }
    __syncthreads();

    if (t < NPTS) {
        float sx = expf(anc[3]), sy2 = expf(anc[4]), sz = expf(anc[5]);
        float k0, k1, k2;
        if (t < 7) {
            k0 = c_FIX[t][0] * sx; k1 = c_FIX[t][1] * sy2; k2 = c_FIX[t][2] * sz;
        } else {
            int q = t - 7;
            k0 = ls_sh[q * 3] * sx; k1 = ls_sh[q * 3 + 1] * sy2; k2 = ls_sh[q * 3 + 2] * sz;
        }
        float s6 = anc[6], c7 = anc[7];
        kp_sh[t * 3]     = c7 * k0 - s6 * k1 + anc[0];
        kp_sh[t * 3 + 1] = s6 * k0 + c7 * k1 + anc[1];
        kp_sh[t * 3 + 2] = k2 + anc[2];
    }
    __syncthreads();

    if (t < 78) {
        int c = t / NPTS, p = t % NPTS;
        const float* P4 = pr + c * 16;
        float px = kp_sh[p * 3], py = kp_sh[p * 3 + 1], pz = kp_sh[p * 3 + 2];
        float X = P4[0] * px + P4[1] * py + P4[2] * pz + P4[3];
        float Y = P4[4] * px + P4[5] * py + P4[6] * pz + P4[7];
        float Z = P4[8] * px + P4[9] * py + P4[10] * pz + P4[11];
        Z = fmaxf(Z, 1e-5f);
        float iz = 1.f / Z;
        u_sh[t] = X * iz / whs[c * 2];
        v_sh[t] = Y * iz / whs[c * 2 + 1];
    }
    __syncthreads();

    /* sample metadata: offsets + bilinear*validity weights */
    for (int s = t; s < SPA; s += 256) {
        int c = s / 52, r = s % 52, l = r / NPTS, p = r % NPTS;
        float u = u_sh[c * NPTS + p], v = v_sh[c * NPTS + p];
        int W = c_W[l], H = c_H[l];
        float gx = u * (float)W - 0.5f;
        float gy = v * (float)H - 0.5f;
        float x0f = floorf(gx), y0f = floorf(gy);
        float wx1 = gx - x0f, wy1 = gy - y0f;
        float wx0 = 1.f - wx1, wy0 = 1.f - wy1;
        int pixbase = (b * NCAMS + c) * H * W;
        float tw[4] = {wx0 * wy0, wx1 * wy0, wx0 * wy1, wx1 * wy1};
        float xs[4] = {x0f, x0f + 1.f, x0f, x0f + 1.f};
        float ys[4] = {y0f, y0f, y0f + 1.f, y0f + 1.f};
        int idx4 = (a * SPA + s) * 4;
#pragma unroll
        for (int i = 0; i < 4; i++) {
            float xf = xs[i], yf = ys[i];
            bool ok = (xf >= 0.f) && (xf < (float)W) && (yf >= 0.f) && (yf < (float)H);
            int off = 0; float w = 0.f;
            if (ok) {
                off = c_base[l] + (pixbase + (int)yf * W + (int)xf) * 256;
                w = tw[i];
            }
            g_soff[idx4 + i] = off;
            g_sw[idx4 + i] = w;
        }
    }

    /* softmax over 312 (c,l,p) per group: warp g handles group g */
    int g = t >> 5, lane = t & 31;
    const float* ceWb = g_ceW + b * NCAMS * JW;
    float mx = -1e30f;
    for (int s = lane; s < SPA; s += 32) {
        int c = s / 52; int j = (s % 52) * NG + g;
        float v = fw_sh[j] + ceWb[c * JW + j];
        mx = fmaxf(mx, v);
    }
    for (int o = 16; o > 0; o >>= 1) mx = fmaxf(mx, __shfl_xor_sync(0xffffffffu, mx, o));
    float sum = 0.f;
    for (int s = lane; s < SPA; s += 32) {
        int c = s / 52; int j = (s % 52) * NG + g;
        float v = fw_sh[j] + ceWb[c * JW + j];
        float e = __expf(v - mx);
        esh[g * SPA + s] = e;
        sum += e;
    }
    for (int o = 16; o > 0; o >>= 1) sum += __shfl_xor_sync(0xffffffffu, sum, o);
    float inv = 1.f / sum;
    for (int s = lane; s < SPA; s += 32)
        g_wg[a * (SPA * NG) + s * NG + g] = esh[g * SPA + s] * inv;
}

/* ------------- gather + fuse (fp16 taps, half2 lanes, 2-way sample split) ------------- */
__global__ void k_sample() {
    int a = blockIdx.x, t = threadIdx.x;
    int hh = t >> 7;          /* sample-split half: 0/1 */
    int c2 = t & 127;         /* channel pair index: ch = 2*c2, 2*c2+1 */
    int g = c2 >> 4;          /* group (32 channels per group) */
    __shared__ int soff[SPA * 4];
    __shared__ float sw[SPA * 4];
    __shared__ float wg[SPA * NG];
    __shared__ float red[256];
    for (int i = t; i < SPA * 4; i += 256) {
        soff[i] = g_soff[a * SPA * 4 + i];
        sw[i] = g_sw[a * SPA * 4 + i];
    }
    for (int i = t; i < SPA * NG; i += 256) wg[i] = g_wg[a * SPA * NG + i];
    __syncthreads();

    float acc0 = 0.f, acc1 = 0.f;
    const __half* fmt = g_fmt;
    for (int s = hh; s < SPA; s += 2) {
        float w0 = sw[s * 4], w1 = sw[s * 4 + 1], w2 = sw[s * 4 + 2], w3 = sw[s * 4 + 3];
        if (w0 == 0.f && w1 == 0.f && w2 == 0.f && w3 == 0.f) continue;
        float wq = wg[s * NG + g];
        float v0 = 0.f, v1 = 0.f;
        if (w0 != 0.f) {
            float2 f = __half22float2(*(const __half2*)(fmt + soff[s * 4] + 2 * c2));
            v0 += w0 * f.x; v1 += w0 * f.y;
        }
        if (w1 != 0.f) {
            float2 f = __half22float2(*(const __half2*)(fmt + soff[s * 4 + 1] + 2 * c2));
            v0 += w1 * f.x; v1 += w1 * f.y;
        }
        if (w2 != 0.f) {
            float2 f = __half22float2(*(const __half2*)(fmt + soff[s * 4 + 2] + 2 * c2));
            v0 += w2 * f.x; v1 += w2 * f.y;
        }
        if (w3 != 0.f) {
            float2 f = __half22float2(*(const __half2*)(fmt + soff[s * 4 + 3] + 2 * c2));
            v0 += w3 * f.x; v1 += w3 * f.y;
        }
        acc0 += wq * v0; acc1 += wq * v1;
    }
    if (hh == 1) { red[c2 * 2] = acc0; red[c2 * 2 + 1] = acc1; }
    __syncthreads();
    if (hh == 0) {
        g_fused[a * 256 + 2 * c2]     = acc0 + red[c2 * 2];
        g_fused[a * 256 + 2 * c2 + 1] = acc1 + red[c2 * 2 + 1];
    }
}

/* ------------- output projection + concat instance_feature ------------- */
__global__ void k_out(const float* __restrict__ instf,
                      const float* __restrict__ opw,
                      const float* __restrict__ opb,
                      float* __restrict__ out) {
    int a0 = blockIdx.x * 8;
    int t = threadIdx.x;
    __shared__ float f[8][256];
#pragma unroll
    for (int aa = 0; aa < 8; aa++) f[aa][t] = g_fused[(a0 + aa) * 256 + t];
    __syncthreads();
    float acc[8];
#pragma unroll
    for (int aa = 0; aa < 8; aa++) acc[aa] = opb[t];
    for (int k = 0; k < 256; k++) {
        float w = opw[k * 256 + t];
#pragma unroll
        for (int aa = 0; aa < 8; aa++) acc[aa] += f[aa][k] * w;
    }
#pragma unroll
    for (int aa = 0; aa < 8; aa++) {
        out[(size_t)(a0 + aa) * 512 + t] = acc[aa];
        out[(size_t)(a0 + aa) * 512 + 256 + t] = instf[(a0 + aa) * 256 + t];
    }
}

extern "C" void kernel_launch(void* const* d_in, const int* in_sizes, int n_in,
                              void* d_out, int out_size) {
    const float* instf = (const float*)d_in[0];
    const float* anchor = (const float*)d_in[1];
    const float* ae = (const float*)d_in[2];
    const float *fm0, *fm1, *fm2, *fm3, *proj, *wh;
    if (in_sizes[3] == 192) {           /* setup_inputs dict order */
        proj = (const float*)d_in[3];
        wh   = (const float*)d_in[4];
        fm0  = (const float*)d_in[5];
        fm1  = (const float*)d_in[6];
        fm2  = (const float*)d_in[7];
        fm3  = (const float*)d_in[8];
    } else {                             /* reference signature order */
        fm0  = (const float*)d_in[3];
        fm1  = (const float*)d_in[4];
        fm2  = (const float*)d_in[5];
        fm3  = (const float*)d_in[6];
        proj = (const float*)d_in[7];
        wh   = (const float*)d_in[8];
    }
    const float* lfcw = (const float*)d_in[9];
    const float* lfcb = (const float*)d_in[10];
    const float* ce1w = (const float*)d_in[11];
    const float* ce1b = (const float*)d_in[12];
    const float* ln1g = (const float*)d_in[13];
    const float* ln1b = (const float*)d_in[14];
    const float* ce2w = (const float*)d_in[15];
    const float* ce2b = (const float*)d_in[16];
    const float* ln2g = (const float*)d_in[17];
    const float* ln2b = (const float*)d_in[18];
    const float* wfcw = (const float*)d_in[19];
    const float* wfcb = (const float*)d_in[20];
    const float* opw = (const float*)d_in[21];
    const float* opb = (const float*)d_in[22];
    float* out = (float*)d_out;

    dim3 tb(32, 8);
    k_transpose<<<dim3((11264 + 31) / 32, 4, 12), tb>>>(fm0, 11264, 0);
    k_transpose<<<dim3((2816 + 31) / 32, 4, 12), tb>>>(fm1, 2816, 34603008);
    k_transpose<<<dim3((704 + 31) / 32, 4, 12), tb>>>(fm2, 704, 43253760);
    k_transpose<<<dim3((176 + 31) / 32, 4, 12), tb>>>(fm3, 176, 45416448);
    k_cam<<<12, 256>>>(proj, ce1w, ce1b, ln1g, ln1b, ce2w, ce2b, ln2g, ln2b, wfcw, wfcb);
    k_featw<<<NATOT / 8, 256>>>(instf, ae, wfcw);
    k_prep<<<NATOT, 256>>>(anchor, instf, proj, wh, lfcw, lfcb);
    k_sample<<<NATOT, 256>>>();
    k_out<<<NATOT / 8, 256>>>(instf, opw, opb, out);
}

// round 10
// speedup vs baseline: 1.3610x; 1.1840x over previous
#include <cuda_runtime.h>
#include <cuda_fp16.h>
#include <math.h>

#define E 256
#define NCAMS 6
#define NLVL 4
#define NPTS 13
#define NG 8
#define NA 900
#define BS 2
#define NATOT (BS*NA)          /* 1800 */
#define SPA (NCAMS*NLVL*NPTS)  /* 312 */
#define JW (NLVL*NPTS*NG)      /* 416 */

/* transposed feature maps (fp16): concat over levels of [12][P_l][256] */
#define FMT_TOTAL 45957120
__device__ __half g_fmt[FMT_TOTAL];
__device__ float g_ceW[BS*NCAMS*JW];       /* includes wfc_b */
__device__ float g_featw[NATOT*JW];
__device__ float g_fused[NATOT*E];

/* transpose block ranges: nx_l = P_l/32, each level has nx*4*12 blocks */
#define TRB0 16896      /* 352*48 */
#define TRB1 21120      /* +88*48 */
#define TRB2 22176      /* +22*48 */
#define TRB3 22464      /* +6*48  */
#define NBLK_CAM 12
#define NBLK_FW  (NATOT/8)   /* 225 */
#define PH1_BLOCKS (TRB3 + NBLK_CAM + NBLK_FW)

__constant__ int   c_W[4]    = {176, 88, 44, 22};
__constant__ int   c_H[4]    = {64, 32, 16, 8};
__constant__ int   c_base[4] = {0, 34603008, 43253760, 45416448};
__constant__ float c_FIX[7][3] = {
    {0.f,0.f,0.f},{0.45f,0.f,0.f},{-0.45f,0.f,0.f},{0.f,0.45f,0.f},
    {0.f,-0.45f,0.f},{0.f,0.f,0.45f},{0.f,0.f,-0.45f}};

__device__ __forceinline__ float block_reduce_sum(float v, float* red) {
    __syncthreads();
    for (int o = 16; o > 0; o >>= 1) v += __shfl_xor_sync(0xffffffffu, v, o);
    if ((threadIdx.x & 31) == 0) red[threadIdx.x >> 5] = v;
    __syncthreads();
    float s = 0.f;
#pragma unroll
    for (int i = 0; i < 8; i++) s += red[i];
    return s;
}

/* ------------- phase 1 fat kernel: transposes + cam embed + featW ------------- */
__global__ void k_phase1(const float* __restrict__ fm0, const float* __restrict__ fm1,
                         const float* __restrict__ fm2, const float* __restrict__ fm3,
                         const float* __restrict__ proj,
                         const float* __restrict__ ce1w, const float* __restrict__ ce1b,
                         const float* __restrict__ ln1g, const float* __restrict__ ln1b,
                         const float* __restrict__ ce2w, const float* __restrict__ ce2b,
                         const float* __restrict__ ln2g, const float* __restrict__ ln2b,
                         const float* __restrict__ wfcw, const float* __restrict__ wfcb,
                         const float* __restrict__ instf, const float* __restrict__ ae) {
    __shared__ float tile[64][33];      /* transpose staging (aliased by nothing) */
    __shared__ float fsh[8][256];       /* featw tile */
    __shared__ float red[8];
    int bid = blockIdx.x;
    int t = threadIdx.x;

    if (bid < TRB3) {
        /* ---- transpose path ---- */
        int l, local;
        const float* src;
        if (bid < TRB0)      { l = 0; local = bid;        src = fm0; }
        else if (bid < TRB1) { l = 1; local = bid - TRB0; src = fm1; }
        else if (bid < TRB2) { l = 2; local = bid - TRB1; src = fm2; }
        else                 { l = 3; local = bid - TRB2; src = fm3; }
        int P = c_W[l] * c_H[l];
        int nx = P >> 5;                /* P is a multiple of 32 for all levels */
        int bc = local / (nx * 4);
        int rem = local - bc * (nx * 4);
        int chb = rem / nx;
        int px = rem - chb * nx;
        int ch0 = chb * 64;
        int p0 = px * 32;
        int tx = t & 31, ty = t >> 5;
        const float* s = src + (size_t)bc * 256 * P;
        __half* d = g_fmt + c_base[l] + (size_t)bc * P * 256;
        int p = p0 + tx;
#pragma unroll
        for (int r = 0; r < 8; r++) {
            int chl = ty + r * 8;
            tile[chl][tx] = s[(size_t)(ch0 + chl) * P + p];
        }
        __syncthreads();
#pragma unroll
        for (int r = 0; r < 4; r++) {
            int pl = ty + r * 8;
            __half2 h = __float22half2_rn(make_float2(tile[2 * tx][pl], tile[2 * tx + 1][pl]));
            *(__half2*)(d + (size_t)(p0 + pl) * 256 + ch0 + 2 * tx) = h;
        }
    } else if (bid < TRB3 + NBLK_CAM) {
        /* ---- camera embedding -> ceW ---- */
        int bc = bid - TRB3;
        __shared__ float cam[12];
        __shared__ float h[256];
        if (t < 12) cam[t] = proj[bc * 16 + t];
        __syncthreads();

        float x = ce1b[t];
        for (int k = 0; k < 12; k++) x += cam[k] * ce1w[k * 256 + t];
        x = fmaxf(x, 0.f);
        {
            float m = block_reduce_sum(x, red) * (1.f / 256.f);
            float dd = x - m;
            float var = block_reduce_sum(dd * dd, red) * (1.f / 256.f);
            x = dd * rsqrtf(var + 1e-5f) * ln1g[t] + ln1b[t];
        }
        __syncthreads();
        h[t] = x;
        __syncthreads();

        float y = ce2b[t];
        for (int k = 0; k < 256; k++) y += h[k] * ce2w[k * 256 + t];
        y = fmaxf(y, 0.f);
        {
            float m = block_reduce_sum(y, red) * (1.f / 256.f);
            float dd = y - m;
            float var = block_reduce_sum(dd * dd, red) * (1.f / 256.f);
            y = dd * rsqrtf(var + 1e-5f) * ln2g[t] + ln2b[t];
        }
        __syncthreads();
        h[t] = y;
        __syncthreads();

        for (int j = t; j < JW; j += 256) {
            float a = wfcb[j];
            for (int k = 0; k < 256; k++) a += h[k] * wfcw[k * JW + j];
            g_ceW[bc * JW + j] = a;
        }
    } else {
        /* ---- featW = (inst + ae) @ wfc_w, 8 anchors ---- */
        int a0 = (bid - TRB3 - NBLK_CAM) * 8;
#pragma unroll
        for (int aa = 0; aa < 8; aa++)
            fsh[aa][t] = instf[(a0 + aa) * 256 + t] + ae[(a0 + aa) * 256 + t];
        __syncthreads();
        for (int j = t; j < JW; j += 256) {
            float acc[8];
#pragma unroll
            for (int aa = 0; aa < 8; aa++) acc[aa] = 0.f;
            for (int k = 0; k < 256; k++) {
                float w = wfcw[k * JW + j];
#pragma unroll
                for (int aa = 0; aa < 8; aa++) acc[aa] += fsh[aa][k] * w;
            }
#pragma unroll
            for (int aa = 0; aa < 8; aa++) g_featw[(a0 + aa) * JW + j] = acc[aa];
        }
    }
}

/* ------------- fused prep + gather: block per anchor ------------- */
__global__ void k_fuse(const float* __restrict__ anchor,
                       const float* __restrict__ instf,
                       const float* __restrict__ proj,
                       const float* __restrict__ wh,
                       const float* __restrict__ lfcw,
                       const float* __restrict__ lfcb) {
    int a = blockIdx.x;
    int b = a / NA;
    int t = threadIdx.x;
    __shared__ float if_sh[256];
    __shared__ float fw_sh[JW];
    __shared__ float anc[11];
    __shared__ float ls_sh[18];
    __shared__ float kp_sh[39];
    __shared__ float u_sh[78], v_sh[78];
    __shared__ float pr[96];
    __shared__ float whs[12];
    __shared__ int   soff[SPA * 4];
    __shared__ float sw[SPA * 4];
    __shared__ float wg[SPA * NG];
    __shared__ float4 red4[3 * 64];

    if_sh[t] = instf[a * 256 + t];
    fw_sh[t] = g_featw[a * JW + t];
    if (t < JW - 256) fw_sh[t + 256] = g_featw[a * JW + 256 + t];
    if (t < 11) anc[t] = anchor[a * 11 + t];
    if (t < 96) pr[t] = proj[b * 96 + t];
    if (t < 12) whs[t] = wh[b * 12 + t];
    __syncthreads();

    if (t < 18) {
        float s = lfcb[t];
        for (int k = 0; k < 256; k++) s += if_sh[k] * lfcw[k * 18 + t];
        ls_sh[t] = 1.f / (1.f + expf(-s)) - 0.5f;
    }
    __syncthreads();

    if (t < NPTS) {
        float sx = expf(anc[3]), sy2 = expf(anc[4]), sz = expf(anc[5]);
        float k0, k1, k2;
        if (t < 7) {
            k0 = c_FIX[t][0] * sx; k1 = c_FIX[t][1] * sy2; k2 = c_FIX[t][2] * sz;
        } else {
            int q = t - 7;
            k0 = ls_sh[q * 3] * sx; k1 = ls_sh[q * 3 + 1] * sy2; k2 = ls_sh[q * 3 + 2] * sz;
        }
        float s6 = anc[6], c7 = anc[7];
        kp_sh[t * 3]     = c7 * k0 - s6 * k1 + anc[0];
        kp_sh[t * 3 + 1] = s6 * k0 + c7 * k1 + anc[1];
        kp_sh[t * 3 + 2] = k2 + anc[2];
    }
    __syncthreads();

    if (t < 78) {
        int c = t / NPTS, p = t % NPTS;
        const float* P4 = pr + c * 16;
        float px = kp_sh[p * 3], py = kp_sh[p * 3 + 1], pz = kp_sh[p * 3 + 2];
        float X = P4[0] * px + P4[1] * py + P4[2] * pz + P4[3];
        float Y = P4[4] * px + P4[5] * py + P4[6] * pz + P4[7];
        float Z = P4[8] * px + P4[9] * py + P4[10] * pz + P4[11];
        Z = fmaxf(Z, 1e-5f);
        float iz = 1.f / Z;
        u_sh[t] = X * iz / whs[c * 2];
        v_sh[t] = Y * iz / whs[c * 2 + 1];
    }
    __syncthreads();

    /* sample metadata into smem */
    for (int s = t; s < SPA; s += 256) {
        int c = s / 52, r = s % 52, l = r / NPTS, p = r % NPTS;
        float u = u_sh[c * NPTS + p], v = v_sh[c * NPTS + p];
        int W = c_W[l], H = c_H[l];
        float gx = u * (float)W - 0.5f;
        float gy = v * (float)H - 0.5f;
        float x0f = floorf(gx), y0f = floorf(gy);
        float wx1 = gx - x0f, wy1 = gy - y0f;
        float wx0 = 1.f - wx1, wy0 = 1.f - wy1;
        int pixbase = (b * NCAMS + c) * H * W;
        float tw[4] = {wx0 * wy0, wx1 * wy0, wx0 * wy1, wx1 * wy1};
        float xs[4] = {x0f, x0f + 1.f, x0f, x0f + 1.f};
        float ys[4] = {y0f, y0f, y0f + 1.f, y0f + 1.f};
#pragma unroll
        for (int i = 0; i < 4; i++) {
            float xf = xs[i], yf = ys[i];
            bool ok = (xf >= 0.f) && (xf < (float)W) && (yf >= 0.f) && (yf < (float)H);
            int off = 0; float w = 0.f;
            if (ok) {
                off = c_base[l] + (pixbase + (int)yf * W + (int)xf) * 256;
                w = tw[i];
            }
            soff[s * 4 + i] = off;
            sw[s * 4 + i] = w;
        }
    }

    /* softmax over 312 samples per group: warp g handles group g (in-place in wg) */
    {
        int g = t >> 5, lane = t & 31;
        const float* ceWb = g_ceW + b * NCAMS * JW;
        float mx = -1e30f;
        for (int s = lane; s < SPA; s += 32) {
            int c = s / 52; int j = (s % 52) * NG + g;
            float v = fw_sh[j] + ceWb[c * JW + j];
            mx = fmaxf(mx, v);
        }
        for (int o = 16; o > 0; o >>= 1) mx = fmaxf(mx, __shfl_xor_sync(0xffffffffu, mx, o));
        float sum = 0.f;
        for (int s = lane; s < SPA; s += 32) {
            int c = s / 52; int j = (s % 52) * NG + g;
            float v = fw_sh[j] + ceWb[c * JW + j];
            float e = __expf(v - mx);
            wg[s * NG + g] = e;
            sum += e;
        }
        for (int o = 16; o > 0; o >>= 1) sum += __shfl_xor_sync(0xffffffffu, sum, o);
        float inv = 1.f / sum;
        for (int s = lane; s < SPA; s += 32) wg[s * NG + g] *= inv;
    }
    __syncthreads();

    /* gather: 4-way sample split, 4 channels (8B) per thread */
    int split = t >> 6, c4 = t & 63, g = c4 >> 3;
    float a0 = 0.f, a1 = 0.f, a2 = 0.f, a3 = 0.f;
    const __half* fmt = g_fmt;
    for (int s = split; s < SPA; s += 4) {
        float w0 = sw[s * 4], w1 = sw[s * 4 + 1], w2 = sw[s * 4 + 2], w3 = sw[s * 4 + 3];
        if (w0 == 0.f && w1 == 0.f && w2 == 0.f && w3 == 0.f) continue;
        float wq = wg[s * NG + g];
        float v0 = 0.f, v1 = 0.f, v2 = 0.f, v3 = 0.f;
        if (w0 != 0.f) {
            uint2 r = *(const uint2*)(fmt + soff[s * 4] + 4 * c4);
            float2 fa = __half22float2(*(__half2*)&r.x), fb = __half22float2(*(__half2*)&r.y);
            v0 += w0 * fa.x; v1 += w0 * fa.y; v2 += w0 * fb.x; v3 += w0 * fb.y;
        }
        if (w1 != 0.f) {
            uint2 r = *(const uint2*)(fmt + soff[s * 4 + 1] + 4 * c4);
            float2 fa = __half22float2(*(__half2*)&r.x), fb = __half22float2(*(__half2*)&r.y);
            v0 += w1 * fa.x; v1 += w1 * fa.y; v2 += w1 * fb.x; v3 += w1 * fb.y;
        }
        if (w2 != 0.f) {
            uint2 r = *(const uint2*)(fmt + soff[s * 4 + 2] + 4 * c4);
            float2 fa = __half22float2(*(__half2*)&r.x), fb = __half22float2(*(__half2*)&r.y);
            v0 += w2 * fa.x; v1 += w2 * fa.y; v2 += w2 * fb.x; v3 += w2 * fb.y;
        }
        if (w3 != 0.f) {
            uint2 r = *(const uint2*)(fmt + soff[s * 4 + 3] + 4 * c4);
            float2 fa = __half22float2(*(__half2*)&r.x), fb = __half22float2(*(__half2*)&r.y);
            v0 += w3 * fa.x; v1 += w3 * fa.y; v2 += w3 * fb.x; v3 += w3 * fb.y;
        }
        a0 += wq * v0; a1 += wq * v1; a2 += wq * v2; a3 += wq * v3;
    }
    if (split) red4[(split - 1) * 64 + c4] = make_float4(a0, a1, a2, a3);
    __syncthreads();
    if (split == 0) {
#pragma unroll
        for (int i = 0; i < 3; i++) {
            float4 r = red4[i * 64 + c4];
            a0 += r.x; a1 += r.y; a2 += r.z; a3 += r.w;
        }
        *(float4*)(g_fused + a * 256 + 4 * c4) = make_float4(a0, a1, a2, a3);
    }
}

/* ------------- output projection + concat instance_feature ------------- */
__global__ void k_out(const float* __restrict__ instf,
                      const float* __restrict__ opw,
                      const float* __restrict__ opb,
                      float* __restrict__ out) {
    int a0 = blockIdx.x * 8;
    int t = threadIdx.x;
    __shared__ float f[8][256];
#pragma unroll
    for (int aa = 0; aa < 8; aa++) f[aa][t] = g_fused[(a0 + aa) * 256 + t];
    __syncthreads();
    float acc[8];
#pragma unroll
    for (int aa = 0; aa < 8; aa++) acc[aa] = opb[t];
    for (int k = 0; k < 256; k++) {
        float w = opw[k * 256 + t];
#pragma unroll
        for (int aa = 0; aa < 8; aa++) acc[aa] += f[aa][k] * w;
    }
#pragma unroll
    for (int aa = 0; aa < 8; aa++) {
        out[(size_t)(a0 + aa) * 512 + t] = acc[aa];
        out[(size_t)(a0 + aa) * 512 + 256 + t] = instf[(a0 + aa) * 256 + t];
    }
}

extern "C" void kernel_launch(void* const* d_in, const int* in_sizes, int n_in,
                              void* d_out, int out_size) {
    const float* instf = (const float*)d_in[0];
    const float* anchor = (const float*)d_in[1];
    const float* ae = (const float*)d_in[2];
    const float *fm0, *fm1, *fm2, *fm3, *proj, *wh;
    if (in_sizes[3] == 192) {           /* setup_inputs dict order */
        proj = (const float*)d_in[3];
        wh   = (const float*)d_in[4];
        fm0  = (const float*)d_in[5];
        fm1  = (const float*)d_in[6];
        fm2  = (const float*)d_in[7];
        fm3  = (const float*)d_in[8];
    } else {                             /* reference signature order */
        fm0  = (const float*)d_in[3];
        fm1  = (const float*)d_in[4];
        fm2  = (const float*)d_in[5];
        fm3  = (const float*)d_in[6];
        proj = (const float*)d_in[7];
        wh   = (const float*)d_in[8];
    }
    const float* lfcw = (const float*)d_in[9];
    const float* lfcb = (const float*)d_in[10];
    const float* ce1w = (const float*)d_in[11];
    const float* ce1b = (const float*)d_in[12];
    const float* ln1g = (const float*)d_in[13];
    const float* ln1b = (const float*)d_in[14];
    const float* ce2w = (const float*)d_in[15];
    const float* ce2b = (const float*)d_in[16];
    const float* ln2g = (const float*)d_in[17];
    const float* ln2b = (const float*)d_in[18];
    const float* wfcw = (const float*)d_in[19];
    const float* wfcb = (const float*)d_in[20];
    const float* opw = (const float*)d_in[21];
    const float* opb = (const float*)d_in[22];
    float* out = (float*)d_out;

    k_phase1<<<PH1_BLOCKS, 256>>>(fm0, fm1, fm2, fm3, proj,
                                  ce1w, ce1b, ln1g, ln1b, ce2w, ce2b, ln2g, ln2b,
                                  wfcw, wfcb, instf, ae);
    k_fuse<<<NATOT, 256>>>(anchor, instf, proj, wh, lfcw, lfcb);
    k_out<<<NATOT / 8, 256>>>(instf, opw, opb, out);
}

// round 13
// speedup vs baseline: 1.3837x; 1.0167x over previous
#include <cuda_runtime.h>
#include <cuda_fp16.h>
#include <math.h>

#define E 256
#define NCAMS 6
#define NLVL 4
#define NPTS 13
#define NG 8
#define NA 900
#define BS 2
#define NATOT (BS*NA)          /* 1800 */
#define SPA (NCAMS*NLVL*NPTS)  /* 312 */
#define JW (NLVL*NPTS*NG)      /* 416 */

/* transposed feature maps (fp16): concat over levels of [12][P_l][256] */
#define FMT_TOTAL 45957120
__device__ __half g_fmt[FMT_TOTAL];
__device__ float g_ceW[BS*NCAMS*JW];       /* includes wfc_b */
__device__ float g_featw[NATOT*JW];
__device__ float g_fused[NATOT*E];

/* transpose block ranges: nx_l = ceil(P_l/64), each level has nx*4*12 blocks */
#define TRB0 8448       /* 176*48 */
#define TRB1 10560      /* +44*48 */
#define TRB2 11088      /* +11*48 */
#define TRB3 11232      /* +3*48  */
#define NBLK_CAM 12
#define NBLK_FW  (NATOT/8)   /* 225 */
#define PH1_BLOCKS (TRB3 + NBLK_CAM + NBLK_FW)

__constant__ int   c_W[4]    = {176, 88, 44, 22};
__constant__ int   c_H[4]    = {64, 32, 16, 8};
__constant__ int   c_base[4] = {0, 34603008, 43253760, 45416448};
__constant__ int   c_nx[4]   = {176, 44, 11, 3};
__constant__ float c_FIX[7][3] = {
    {0.f,0.f,0.f},{0.45f,0.f,0.f},{-0.45f,0.f,0.f},{0.f,0.45f,0.f},
    {0.f,-0.45f,0.f},{0.f,0.f,0.45f},{0.f,0.f,-0.45f}};

__device__ __forceinline__ float block_reduce_sum(float v, float* red) {
    __syncthreads();
    for (int o = 16; o > 0; o >>= 1) v += __shfl_xor_sync(0xffffffffu, v, o);
    if ((threadIdx.x & 31) == 0) red[threadIdx.x >> 5] = v;
    __syncthreads();
    float s = 0.f;
#pragma unroll
    for (int i = 0; i < 8; i++) s += red[i];
    return s;
}

/* ------------- phase 1 fat kernel: transposes + cam embed + featW ------------- */
__global__ void __launch_bounds__(256) k_phase1(
                         const float* __restrict__ fm0, const float* __restrict__ fm1,
                         const float* __restrict__ fm2, const float* __restrict__ fm3,
                         const float* __restrict__ proj,
                         const float* __restrict__ ce1w, const float* __restrict__ ce1b,
                         const float* __restrict__ ln1g, const float* __restrict__ ln1b,
                         const float* __restrict__ ce2w, const float* __restrict__ ce2b,
                         const float* __restrict__ ln2g, const float* __restrict__ ln2b,
                         const float* __restrict__ wfcw, const float* __restrict__ wfcb,
                         const float* __restrict__ instf, const float* __restrict__ ae) {
    __shared__ float tile[64][65];      /* transpose staging: 64 ch x 64 p */
    __shared__ float red[8];
    int bid = blockIdx.x;
    int t = threadIdx.x;

    if (bid < TRB3) {
        /* ---- transpose path: 64ch x 64p tile, LDG.128 in / STG.64 out ---- */
        int l, local;
        const float* src;
        if (bid < TRB0)      { l = 0; local = bid;        src = fm0; }
        else if (bid < TRB1) { l = 1; local = bid - TRB0; src = fm1; }
        else if (bid < TRB2) { l = 2; local = bid - TRB1; src = fm2; }
        else                 { l = 3; local = bid - TRB2; src = fm3; }
        int P = c_W[l] * c_H[l];
        int nx = c_nx[l];
        int bc = local / (nx * 4);
        int rem = local - bc * (nx * 4);
        int chb = rem / nx;
        int px = rem - chb * nx;
        int ch0 = chb * 64;
        int p0 = px * 64;
        const float* s = src + (size_t)bc * 256 * P;
        __half* d = g_fmt + c_base[l] + (size_t)bc * P * 256;

        /* load: thread -> row r = t>>2, quarter q = t&3; 4 x float4 along p */
        {
            int r = t >> 2, q = t & 3;
            const float* srow = s + (size_t)(ch0 + r) * P + p0 + q * 16;
#pragma unroll
            for (int j = 0; j < 4; j++) {
                int pl = q * 16 + j * 4;
                if (p0 + pl < P) {
                    float4 f = *(const float4*)(srow + j * 4);
                    tile[r][pl]     = f.x;
                    tile[r][pl + 1] = f.y;
                    tile[r][pl + 2] = f.z;
                    tile[r][pl + 3] = f.w;
                }
            }
        }
        __syncthreads();
        /* store: thread -> p-row (t>>4)+16*it, 4 channels (t&15)*4 as uint2 */
        {
            int cidx = (t & 15) * 4;
#pragma unroll
            for (int it = 0; it < 4; it++) {
                int row = (t >> 4) + it * 16;
                if (p0 + row < P) {
                    __half2 h0 = __float22half2_rn(make_float2(tile[cidx][row], tile[cidx + 1][row]));
                    __half2 h1 = __float22half2_rn(make_float2(tile[cidx + 2][row], tile[cidx + 3][row]));
                    uint2 u;
                    u.x = *(unsigned int*)&h0;
                    u.y = *(unsigned int*)&h1;
                    *(uint2*)(d + (size_t)(p0 + row) * 256 + ch0 + cidx) = u;
                }
            }
        }
    } else if (bid < TRB3 + NBLK_CAM) {
        /* ---- camera embedding -> ceW ---- */
        int bc = bid - TRB3;
        __shared__ float cam[12];
        __shared__ float h[256];
        if (t < 12) cam[t] = proj[bc * 16 + t];
        __syncthreads();

        float x = ce1b[t];
        for (int k = 0; k < 12; k++) x += cam[k] * ce1w[k * 256 + t];
        x = fmaxf(x, 0.f);
        {
            float m = block_reduce_sum(x, red) * (1.f / 256.f);
            float dd = x - m;
            float var = block_reduce_sum(dd * dd, red) * (1.f / 256.f);
            x = dd * rsqrtf(var + 1e-5f) * ln1g[t] + ln1b[t];
        }
        __syncthreads();
        h[t] = x;
        __syncthreads();

        float y = ce2b[t];
        for (int k = 0; k < 256; k++) y += h[k] * ce2w[k * 256 + t];
        y = fmaxf(y, 0.f);
        {
            float m = block_reduce_sum(y, red) * (1.f / 256.f);
            float dd = y - m;
            float var = block_reduce_sum(dd * dd, red) * (1.f / 256.f);
            y = dd * rsqrtf(var + 1e-5f) * ln2g[t] + ln2b[t];
        }
        __syncthreads();
        h[t] = y;
        __syncthreads();

        for (int j = t; j < JW; j += 256) {
            float a = wfcb[j];
            for (int k = 0; k < 256; k++) a += h[k] * wfcw[k * JW + j];
            g_ceW[bc * JW + j] = a;
        }
    } else {
        /* ---- featW = (inst + ae) @ wfc_w, 8 anchors ---- */
        int a0 = (bid - TRB3 - NBLK_CAM) * 8;
        __shared__ float fsh[8][256];
#pragma unroll
        for (int aa = 0; aa < 8; aa++)
            fsh[aa][t] = instf[(a0 + aa) * 256 + t] + ae[(a0 + aa) * 256 + t];
        __syncthreads();
        for (int j = t; j < JW; j += 256) {
            float acc[8];
#pragma unroll
            for (int aa = 0; aa < 8; aa++) acc[aa] = 0.f;
            for (int k = 0; k < 256; k++) {
                float w = wfcw[k * JW + j];
#pragma unroll
                for (int aa = 0; aa < 8; aa++) acc[aa] += fsh[aa][k] * w;
            }
#pragma unroll
            for (int aa = 0; aa < 8; aa++) g_featw[(a0 + aa) * JW + j] = acc[aa];
        }
    }
}

/* ------------- fused prep + gather: block per anchor ------------- */
__global__ void k_fuse(const float* __restrict__ anchor,
                       const float* __restrict__ instf,
                       const float* __restrict__ proj,
                       const float* __restrict__ wh,
                       const float* __restrict__ lfcw,
                       const float* __restrict__ lfcb) {
    int a = blockIdx.x;
    int b = a / NA;
    int t = threadIdx.x;
    __shared__ float if_sh[256];
    __shared__ float fw_sh[JW];
    __shared__ float anc[11];
    __shared__ float ls_sh[18];
    __shared__ float kp_sh[39];
    __shared__ float u_sh[78], v_sh[78];
    __shared__ float pr[96];
    __shared__ float whs[12];
    __shared__ int   soff[SPA * 4];
    __shared__ float sw[SPA * 4];
    __shared__ float wg[SPA * NG];
    __shared__ float4 red4[3 * 64];

    if_sh[t] = instf[a * 256 + t];
    fw_sh[t] = g_featw[a * JW + t];
    if (t < JW - 256) fw_sh[t + 256] = g_featw[a * JW + 256 + t];
    if (t < 11) anc[t] = anchor[a * 11 + t];
    if (t < 96) pr[t] = proj[b * 96 + t];
    if (t < 12) whs[t] = wh[b * 12 + t];
    __syncthreads();

    if (t < 18) {
        float s = lfcb[t];
        for (int k = 0; k < 256; k++) s += if_sh[k] * lfcw[k * 18 + t];
        ls_sh[t] = 1.f / (1.f + expf(-s)) - 0.5f;
    }
    __syncthreads();

    if (t < NPTS) {
        float sx = expf(anc[3]), sy2 = expf(anc[4]), sz = expf(anc[5]);
        float k0, k1, k2;
        if (t < 7) {
            k0 = c_FIX[t][0] * sx; k1 = c_FIX[t][1] * sy2; k2 = c_FIX[t][2] * sz;
        } else {
            int q = t - 7;
            k0 = ls_sh[q * 3] * sx; k1 = ls_sh[q * 3 + 1] * sy2; k2 = ls_sh[q * 3 + 2] * sz;
        }
        float s6 = anc[6], c7 = anc[7];
        kp_sh[t * 3]     = c7 * k0 - s6 * k1 + anc[0];
        kp_sh[t * 3 + 1] = s6 * k0 + c7 * k1 + anc[1];
        kp_sh[t * 3 + 2] = k2 + anc[2];
    }
    __syncthreads();

    if (t < 78) {
        int c = t / NPTS, p = t % NPTS;
        const float* P4 = pr + c * 16;
        float px = kp_sh[p * 3], py = kp_sh[p * 3 + 1], pz = kp_sh[p * 3 + 2];
        float X = P4[0] * px + P4[1] * py + P4[2] * pz + P4[3];
        float Y = P4[4] * px + P4[5] * py + P4[6] * pz + P4[7];
        float Z = P4[8] * px + P4[9] * py + P4[10] * pz + P4[11];
        Z = fmaxf(Z, 1e-5f);
        float iz = 1.f / Z;
        u_sh[t] = X * iz / whs[c * 2];
        v_sh[t] = Y * iz / whs[c * 2 + 1];
    }
    __syncthreads();

    /* sample metadata into smem */
    for (int s = t; s < SPA; s += 256) {
        int c = s / 52, r = s % 52, l = r / NPTS, p = r % NPTS;
        float u = u_sh[c * NPTS + p], v = v_sh[c * NPTS + p];
        int W = c_W[l], H = c_H[l];
        float gx = u * (float)W - 0.5f;
        float gy = v * (float)H - 0.5f;
        float x0f = floorf(gx), y0f = floorf(gy);
        float wx1 = gx - x0f, wy1 = gy - y0f;
        float wx0 = 1.f - wx1, wy0 = 1.f - wy1;
        int pixbase = (b * NCAMS + c) * H * W;
        float tw[4] = {wx0 * wy0, wx1 * wy0, wx0 * wy1, wx1 * wy1};
        float xs[4] = {x0f, x0f + 1.f, x0f, x0f + 1.f};
        float ys[4] = {y0f, y0f, y0f + 1.f, y0f + 1.f};
#pragma unroll
        for (int i = 0; i < 4; i++) {
            float xf = xs[i], yf = ys[i];
            bool ok = (xf >= 0.f) && (xf < (float)W) && (yf >= 0.f) && (yf < (float)H);
            int off = 0; float w = 0.f;
            if (ok) {
                off = c_base[l] + (pixbase + (int)yf * W + (int)xf) * 256;
                w = tw[i];
            }
            soff[s * 4 + i] = off;
            sw[s * 4 + i] = w;
        }
    }

    /* softmax over 312 samples per group: warp g handles group g (in-place in wg) */
    {
        int g = t >> 5, lane = t & 31;
        const float* ceWb = g_ceW + b * NCAMS * JW;
        float mx = -1e30f;
        for (int s = lane; s < SPA; s += 32) {
            int c = s / 52; int j = (s % 52) * NG + g;
            float v = fw_sh[j] + ceWb[c * JW + j];
            mx = fmaxf(mx, v);
        }
        for (int o = 16; o > 0; o >>= 1) mx = fmaxf(mx, __shfl_xor_sync(0xffffffffu, mx, o));
        float sum = 0.f;
        for (int s = lane; s < SPA; s += 32) {
            int c = s / 52; int j = (s % 52) * NG + g;
            float v = fw_sh[j] + ceWb[c * JW + j];
            float e = __expf(v - mx);
            wg[s * NG + g] = e;
            sum += e;
        }
        for (int o = 16; o > 0; o >>= 1) sum += __shfl_xor_sync(0xffffffffu, sum, o);
        float inv = 1.f / sum;
        for (int s = lane; s < SPA; s += 32) wg[s * NG + g] *= inv;
    }
    __syncthreads();

    /* gather: 4-way sample split, 4 channels (8B) per thread */
    int split = t >> 6, c4 = t & 63, g = c4 >> 3;
    float a0 = 0.f, a1 = 0.f, a2 = 0.f, a3 = 0.f;
    const __half* fmt = g_fmt;
    for (int s = split; s < SPA; s += 4) {
        float w0 = sw[s * 4], w1 = sw[s * 4 + 1], w2 = sw[s * 4 + 2], w3 = sw[s * 4 + 3];
        if (w0 == 0.f && w1 == 0.f && w2 == 0.f && w3 == 0.f) continue;
        float wq = wg[s * NG + g];
        float v0 = 0.f, v1 = 0.f, v2 = 0.f, v3 = 0.f;
        if (w0 != 0.f) {
            uint2 r = *(const uint2*)(fmt + soff[s * 4] + 4 * c4);
            float2 fa = __half22float2(*(__half2*)&r.x), fb = __half22float2(*(__half2*)&r.y);
            v0 += w0 * fa.x; v1 += w0 * fa.y; v2 += w0 * fb.x; v3 += w0 * fb.y;
        }
        if (w1 != 0.f) {
            uint2 r = *(const uint2*)(fmt + soff[s * 4 + 1] + 4 * c4);
            float2 fa = __half22float2(*(__half2*)&r.x), fb = __half22float2(*(__half2*)&r.y);
            v0 += w1 * fa.x; v1 += w1 * fa.y; v2 += w1 * fb.x; v3 += w1 * fb.y;
        }
        if (w2 != 0.f) {
            uint2 r = *(const uint2*)(fmt + soff[s * 4 + 2] + 4 * c4);
            float2 fa = __half22float2(*(__half2*)&r.x), fb = __half22float2(*(__half2*)&r.y);
            v0 += w2 * fa.x; v1 += w2 * fa.y; v2 += w2 * fb.x; v3 += w2 * fb.y;
        }
        if (w3 != 0.f) {
            uint2 r = *(const uint2*)(fmt + soff[s * 4 + 3] + 4 * c4);
            float2 fa = __half22float2(*(__half2*)&r.x), fb = __half22float2(*(__half2*)&r.y);
            v0 += w3 * fa.x; v1 += w3 * fa.y; v2 += w3 * fb.x; v3 += w3 * fb.y;
        }
        a0 += wq * v0; a1 += wq * v1; a2 += wq * v2; a3 += wq * v3;
    }
    if (split) red4[(split - 1) * 64 + c4] = make_float4(a0, a1, a2, a3);
    __syncthreads();
    if (split == 0) {
#pragma unroll
        for (int i = 0; i < 3; i++) {
            float4 r = red4[i * 64 + c4];
            a0 += r.x; a1 += r.y; a2 += r.z; a3 += r.w;
        }
        *(float4*)(g_fused + a * 256 + 4 * c4) = make_float4(a0, a1, a2, a3);
    }
}

/* ------------- output projection + concat instance_feature ------------- */
__global__ void k_out(const float* __restrict__ instf,
                      const float* __restrict__ opw,
                      const float* __restrict__ opb,
                      float* __restrict__ out) {
    int a0 = blockIdx.x * 8;
    int t = threadIdx.x;
    __shared__ float f[8][256];
#pragma unroll
    for (int aa = 0; aa < 8; aa++) f[aa][t] = g_fused[(a0 + aa) * 256 + t];
    __syncthreads();
    float acc[8];
#pragma unroll
    for (int aa = 0; aa < 8; aa++) acc[aa] = opb[t];
    for (int k = 0; k < 256; k++) {
        float w = opw[k * 256 + t];
#pragma unroll
        for (int aa = 0; aa < 8; aa++) acc[aa] += f[aa][k] * w;
    }
#pragma unroll
    for (int aa = 0; aa < 8; aa++) {
        out[(size_t)(a0 + aa) * 512 + t] = acc[aa];
        out[(size_t)(a0 + aa) * 512 + 256 + t] = instf[(a0 + aa) * 256 + t];
    }
}

extern "C" void kernel_launch(void* const* d_in, const int* in_sizes, int n_in,
                              void* d_out, int out_size) {
    const float* instf = (const float*)d_in[0];
    const float* anchor = (const float*)d_in[1];
    const float* ae = (const float*)d_in[2];
    const float *fm0, *fm1, *fm2, *fm3, *proj, *wh;
    if (in_sizes[3] == 192) {           /* setup_inputs dict order */
        proj = (const float*)d_in[3];
        wh   = (const float*)d_in[4];
        fm0  = (const float*)d_in[5];
        fm1  = (const float*)d_in[6];
        fm2  = (const float*)d_in[7];
        fm3  = (const float*)d_in[8];
    } else {                             /* reference signature order */
        fm0  = (const float*)d_in[3];
        fm1  = (const float*)d_in[4];
        fm2  = (const float*)d_in[5];
        fm3  = (const float*)d_in[6];
        proj = (const float*)d_in[7];
        wh   = (const float*)d_in[8];
    }
    const float* lfcw = (const float*)d_in[9];
    const float* lfcb = (const float*)d_in[10];
    const float* ce1w = (const float*)d_in[11];
    const float* ce1b = (const float*)d_in[12];
    const float* ln1g = (const float*)d_in[13];
    const float* ln1b = (const float*)d_in[14];
    const float* ce2w = (const float*)d_in[15];
    const float* ce2b = (const float*)d_in[16];
    const float* ln2g = (const float*)d_in[17];
    const float* ln2b = (const float*)d_in[18];
    const float* wfcw = (const float*)d_in[19];
    const float* wfcb = (const float*)d_in[20];
    const float* opw = (const float*)d_in[21];
    const float* opb = (const float*)d_in[22];
    float* out = (float*)d_out;

    k_phase1<<<PH1_BLOCKS, 256>>>(fm0, fm1, fm2, fm3, proj,
                                  ce1w, ce1b, ln1g, ln1b, ce2w, ce2b, ln2g, ln2b,
                                  wfcw, wfcb, instf, ae);
    k_fuse<<<NATOT, 256>>>(anchor, instf, proj, wh, lfcw, lfcb);
    k_out<<<NATOT / 8, 256>>>(instf, opw, opb, out);
}